// round 9
// baseline (speedup 1.0000x reference)
#include <cuda_runtime.h>
#include <cuda_fp16.h>
#include <cstdint>

// out[b,t] = cumsum_t( relu(x @ Wh^T + bh) ) + (x @ Wb^T + bb)
//   x [16384,1024] f32, Wh [512,1024] f32, bh[512], Wb[1,1024], bb[1]
//
// fp16 mma.sync m16n8k16. CTA = 32 rows x 512 cols, 256 threads (8 warps,
// warp tile 32x64), 2 CTAs/SM. KCHUNK=32, 32 chunks.
// Wh pre-converted to fp16 FRAGMENT-ORDER in gmem (prepass); B fragments are
// loaded DIRECTLY from L2 via coalesced LDG.128 (no smem staging at all).
// A (x): LDG float4 prefetch -> fp16 convert -> STS into tiny 2-stage xs.
// In-register scan epilogue + fused fp32 base GEMV.

#define DDIM   1024
#define TDIM   512
#define BROWS  16384
#define MTILE  32
#define KCHUNK 32
#define NCH    32
#define NTHREADS 256

// static smem layout (bytes)
#define XS_O   0        // 2 x 2048 fp16 x, fragment order
#define WB_O   4096     // 1024 f32
#define BH_O   8192     // 512 f32
#define BASE_O 10240    // 32 f32
#define SEG_O  10368    // 256 f32
#define SMEM_SZ 11392

__device__ __half g_whs[TDIM * DDIM];  // [chunk c][col-group jg][lane][8 halfs]

__device__ __forceinline__ void mma_f16(float* c, uint32_t a0, uint32_t a1,
                                        uint32_t a2, uint32_t a3,
                                        uint32_t b0, uint32_t b1) {
    asm volatile(
        "mma.sync.aligned.m16n8k16.row.col.f32.f16.f16.f32 "
        "{%0,%1,%2,%3}, {%4,%5,%6,%7}, {%8,%9}, {%0,%1,%2,%3};"
        : "+f"(c[0]), "+f"(c[1]), "+f"(c[2]), "+f"(c[3])
        : "r"(a0), "r"(a1), "r"(a2), "r"(a3), "r"(b0), "r"(b1));
}

// prepass: Wh -> fp16 fragment-order:
//   (t,k): c=k>>5, G=(k>>4)&1, u=(k>>3)&1, lk=(k&7)>>1, w=k&1
//   jg=t>>3, l4=t&7, lane=4*l4+lk, h=4*G+2*u+w
//   half_idx = c*16384 + jg*256 + lane*8 + h
__global__ void __launch_bounds__(256) prep_wh_kernel(const float* __restrict__ Wh) {
    const int t  = blockIdx.x;
    const int k4 = threadIdx.x * 4;
    float4 v = *(const float4*)(Wh + (size_t)t * DDIM + k4);
    const int jg = t >> 3, l4 = t & 7;
    #pragma unroll
    for (int e = 0; e < 4; e++) {
        int k = k4 + e;
        int c = k >> 5, G = (k >> 4) & 1, u = (k >> 3) & 1;
        int lk = (k & 7) >> 1, w = k & 1;
        int lane = 4 * l4 + lk;
        int h = 4 * G + 2 * u + w;
        g_whs[(size_t)c * 16384 + jg * 256 + lane * 8 + h] =
            __float2half_rn(((const float*)&v)[e]);
    }
}

__global__ void __launch_bounds__(NTHREADS, 2)
surv_f16d_kernel(const float* __restrict__ x,
                 const float* __restrict__ bh,
                 const float* __restrict__ Wb,
                 const float* __restrict__ bb,
                 float* __restrict__ out)
{
    __shared__ __align__(16) char smc[SMEM_SZ];
    float* wb_s   = (float*)(smc + WB_O);
    float* bh_s   = (float*)(smc + BH_O);
    float* base_s = (float*)(smc + BASE_O);
    float* seg_s  = (float*)(smc + SEG_O);

    const int tid  = threadIdx.x;
    const int nw   = tid >> 5;         // warp = 64-col group (0..7)
    const int lane = tid & 31;
    const int l4   = lane >> 2;
    const int lk   = lane & 3;
    const int row0 = blockIdx.x * MTILE;

    // B direct-LDG base: chunk c, slice j -> + c*32768 + j*512 (bytes)
    const char* bgm = (const char*)g_whs + nw * 4096 + lane * 16;

    // x convert addressing: row = tid>>3 (0..31), kq = tid&7 (float4 of k)
    const int row = tid >> 3;
    const int kq  = tid & 7;
    const float* xsrc = x + (size_t)(row0 + row) * DDIM + kq * 4;
    const int conv_off = ((row >> 4) * 2 + (kq >> 2)) * 512 +
                         (4 * (row & 7) + 2 * (kq & 1)) * 16 +
                         ((row >> 3) & 1) * 4 + ((kq >> 1) & 1) * 8;

    float acc[2][8][4];
    #pragma unroll
    for (int i = 0; i < 2; i++)
        #pragma unroll
        for (int j = 0; j < 8; j++)
            #pragma unroll
            for (int q = 0; q < 4; q++) acc[i][j][q] = 0.f;
    float bacc = 0.f;

    // preload Wb + bh
    #pragma unroll
    for (int i = 0; i < 4; i++) wb_s[tid + 256 * i] = Wb[tid + 256 * i];
    bh_s[tid]       = bh[tid];
    bh_s[tid + 256] = bh[tid + 256];

    // B fragments for chunk 0
    uint4 LB[8];
    #pragma unroll
    for (int j = 0; j < 8; j++)
        LB[j] = *(const uint4*)(bgm + j * 512);

    __syncthreads();   // wb_s visible

    // chunk0 convert + base; prefetch x chunk1
    float4 px = *(const float4*)(xsrc);
    {
        const float4 wv = *(const float4*)(wb_s + kq * 4);
        bacc = fmaf(px.x, wv.x, bacc); bacc = fmaf(px.y, wv.y, bacc);
        bacc = fmaf(px.z, wv.z, bacc); bacc = fmaf(px.w, wv.w, bacc);
        *(__half2*)(smc + XS_O + conv_off)      = __floats2half2_rn(px.x, px.y);
        *(__half2*)(smc + XS_O + conv_off + 16) = __floats2half2_rn(px.z, px.w);
    }
    px = *(const float4*)(xsrc + KCHUNK);

    #pragma unroll 1
    for (int c = 0; c < NCH; c++) {
        __syncthreads();   // xs(c) visible; xs((c+1)&1) free to overwrite

        if (c + 1 < NCH) {   // base fma + convert chunk c+1 from px regs
            const float4 wv = *(const float4*)(wb_s + (c + 1) * KCHUNK + kq * 4);
            bacc = fmaf(px.x, wv.x, bacc); bacc = fmaf(px.y, wv.y, bacc);
            bacc = fmaf(px.z, wv.z, bacc); bacc = fmaf(px.w, wv.w, bacc);
            char* xb = smc + XS_O + ((c + 1) & 1) * 2048 + conv_off;
            *(__half2*)(xb)      = __floats2half2_rn(px.x, px.y);
            *(__half2*)(xb + 16) = __floats2half2_rn(px.z, px.w);
        }
        if (c + 2 < NCH)
            px = *(const float4*)(xsrc + (c + 2) * KCHUNK);

        // ---- MMA chunk c: A from smem (base+lane*16), B from registers ----
        const char* xaddr = smc + XS_O + (c & 1) * 2048 + lane * 16;
        uint4 LA00 = *(const uint4*)(xaddr);            // i0 G0
        uint4 LA01 = *(const uint4*)(xaddr + 512);      // i0 G1
        uint4 LA10 = *(const uint4*)(xaddr + 1024);     // i1 G0
        uint4 LA11 = *(const uint4*)(xaddr + 1536);     // i1 G1
        #pragma unroll
        for (int j = 0; j < 8; j++) {
            mma_f16(acc[0][j], LA00.x, LA00.y, LA00.z, LA00.w, LB[j].x, LB[j].y);
            mma_f16(acc[1][j], LA10.x, LA10.y, LA10.z, LA10.w, LB[j].x, LB[j].y);
            mma_f16(acc[0][j], LA01.x, LA01.y, LA01.z, LA01.w, LB[j].z, LB[j].w);
            mma_f16(acc[1][j], LA11.x, LA11.y, LA11.z, LA11.w, LB[j].z, LB[j].w);
        }

        // ---- issue B LDGs for chunk c+1 (latency covered by barrier+convert) ----
        if (c + 1 < NCH) {
            const char* bsrc = bgm + (size_t)(c + 1) * 32768;
            #pragma unroll
            for (int j = 0; j < 8; j++)
                LB[j] = *(const uint4*)(bsrc + j * 512);
        }
    }

    // ---- base reduce: 8 lanes (kq) per row ----
    bacc += __shfl_down_sync(0xffffffffu, bacc, 4, 8);
    bacc += __shfl_down_sync(0xffffffffu, bacc, 2, 8);
    bacc += __shfl_down_sync(0xffffffffu, bacc, 1, 8);
    if (kq == 0) base_s[row] = bacc;

    // ---- per-row segmented scan over this warp's 64 cols ----
    float2 bhv[8];
    #pragma unroll
    for (int j = 0; j < 8; j++)
        bhv[j] = *(const float2*)(bh_s + nw * 64 + 8 * j + 2 * lk);

    #pragma unroll
    for (int i = 0; i < 2; i++) {
        #pragma unroll
        for (int hh = 0; hh < 2; hh++) {
            const int r = 16 * i + 8 * hh + l4;
            float carry = 0.f;
            #pragma unroll
            for (int j = 0; j < 8; j++) {
                float v0 = fmaxf(acc[i][j][2 * hh]     + bhv[j].x, 0.f);
                float v1 = fmaxf(acc[i][j][2 * hh + 1] + bhv[j].y, 0.f);
                float p = v0 + v1;
                float incl = p, t;
                t = __shfl_up_sync(0xffffffffu, incl, 1, 4); if (lk >= 1) incl += t;
                t = __shfl_up_sync(0xffffffffu, incl, 2, 4); if (lk >= 2) incl += t;
                float excl = incl - p;
                acc[i][j][2 * hh]     = carry + excl + v0;
                acc[i][j][2 * hh + 1] = carry + incl;
                carry += __shfl_sync(0xffffffffu, incl, 3, 4);
            }
            if (lk == 0) seg_s[r * 8 + nw] = carry;
        }
    }
    __syncthreads();

    // ---- cross-warp segment prefix + base, store ----
    const float bbv = bb[0];
    #pragma unroll
    for (int i = 0; i < 2; i++) {
        #pragma unroll
        for (int hh = 0; hh < 2; hh++) {
            const int r = 16 * i + 8 * hh + l4;
            float g = base_s[r] + bbv;
            #pragma unroll
            for (int s = 0; s < 8; s++)
                if (s < nw) g += seg_s[r * 8 + s];
            float* orow = out + (size_t)(row0 + r) * TDIM + nw * 64 + 2 * lk;
            #pragma unroll
            for (int j = 0; j < 8; j++) {
                float2 o;
                o.x = acc[i][j][2 * hh]     + g;
                o.y = acc[i][j][2 * hh + 1] + g;
                *(float2*)(orow + 8 * j) = o;
            }
        }
    }
}

extern "C" void kernel_launch(void* const* d_in, const int* in_sizes, int n_in,
                              void* d_out, int out_size)
{
    const float* x  = (const float*)d_in[0];
    const float* Wh = (const float*)d_in[1];
    const float* bh = (const float*)d_in[2];
    const float* Wb = (const float*)d_in[3];
    const float* bb = (const float*)d_in[4];
    float* out = (float*)d_out;
    (void)in_sizes; (void)n_in; (void)out_size;

    prep_wh_kernel<<<TDIM, 256>>>(Wh);
    surv_f16d_kernel<<<BROWS / MTILE, NTHREADS>>>(x, bh, Wb, bb, out);
}

// round 10
// speedup vs baseline: 1.0030x; 1.0030x over previous
#include <cuda_runtime.h>
#include <cuda_fp16.h>
#include <cstdint>

// out[b,t] = cumsum_t( relu(x @ Wh^T + bh) ) + (x @ Wb^T + bb)
//   x [16384,1024] f32, Wh [512,1024] f32, bh[512], Wb[1,1024], bb[1]
//
// fp16 mma.sync m16n8k16. CTA = 32 rows x 512 cols, 256 threads (8 warps,
// warp tile 32x64), 2 CTAs/SM. KCHUNK=32, 32 chunks.
// Wh pre-converted to fp16 FRAGMENT-ORDER in gmem (prepass); B fragments
// load DIRECTLY from L1/L2 via coalesced LDG.128, software-pipelined at
// fragment granularity: LB[j] is reloaded for chunk c+1 right after its
// 4 MMAs (a full chunk of slack covers L2 latency).
// A (x): LDG float4 prefetch -> fp16 convert -> STS into tiny 2-stage xs.
// In-register scan epilogue + fused fp32 base GEMV.

#define DDIM   1024
#define TDIM   512
#define BROWS  16384
#define MTILE  32
#define KCHUNK 32
#define NCH    32
#define NTHREADS 256

// static smem layout (bytes)
#define XS_O   0        // 2 x 2048 fp16 x, fragment order
#define WB_O   4096     // 1024 f32
#define BH_O   8192     // 512 f32
#define BASE_O 10240    // 32 f32
#define SEG_O  10368    // 256 f32
#define SMEM_SZ 11392

__device__ __half g_whs[TDIM * DDIM];  // [chunk c][col-group jg][lane][8 halfs]

__device__ __forceinline__ void mma_f16(float* c, uint32_t a0, uint32_t a1,
                                        uint32_t a2, uint32_t a3,
                                        uint32_t b0, uint32_t b1) {
    asm volatile(
        "mma.sync.aligned.m16n8k16.row.col.f32.f16.f16.f32 "
        "{%0,%1,%2,%3}, {%4,%5,%6,%7}, {%8,%9}, {%0,%1,%2,%3};"
        : "+f"(c[0]), "+f"(c[1]), "+f"(c[2]), "+f"(c[3])
        : "r"(a0), "r"(a1), "r"(a2), "r"(a3), "r"(b0), "r"(b1));
}

// prepass: Wh -> fp16 fragment-order:
//   (t,k): c=k>>5, G=(k>>4)&1, u=(k>>3)&1, lk=(k&7)>>1, w=k&1
//   jg=t>>3, l4=t&7, lane=4*l4+lk, h=4*G+2*u+w
//   half_idx = c*16384 + jg*256 + lane*8 + h
__global__ void __launch_bounds__(256) prep_wh_kernel(const float* __restrict__ Wh) {
    const int t  = blockIdx.x;
    const int k4 = threadIdx.x * 4;
    float4 v = *(const float4*)(Wh + (size_t)t * DDIM + k4);
    const int jg = t >> 3, l4 = t & 7;
    #pragma unroll
    for (int e = 0; e < 4; e++) {
        int k = k4 + e;
        int c = k >> 5, G = (k >> 4) & 1, u = (k >> 3) & 1;
        int lk = (k & 7) >> 1, w = k & 1;
        int lane = 4 * l4 + lk;
        int h = 4 * G + 2 * u + w;
        g_whs[(size_t)c * 16384 + jg * 256 + lane * 8 + h] =
            __float2half_rn(((const float*)&v)[e]);
    }
}

__global__ void __launch_bounds__(NTHREADS, 2)
surv_f16e_kernel(const float* __restrict__ x,
                 const float* __restrict__ bh,
                 const float* __restrict__ Wb,
                 const float* __restrict__ bb,
                 float* __restrict__ out)
{
    __shared__ __align__(16) char smc[SMEM_SZ];
    float* wb_s   = (float*)(smc + WB_O);
    float* bh_s   = (float*)(smc + BH_O);
    float* base_s = (float*)(smc + BASE_O);
    float* seg_s  = (float*)(smc + SEG_O);

    const int tid  = threadIdx.x;
    const int nw   = tid >> 5;         // warp = 64-col group (0..7)
    const int lane = tid & 31;
    const int l4   = lane >> 2;
    const int lk   = lane & 3;
    const int row0 = blockIdx.x * MTILE;

    // B direct-LDG base for this warp/lane: chunk c -> + c*32768, slice j -> + j*512
    const char* bgm = (const char*)g_whs + nw * 4096 + lane * 16;

    // x convert addressing: row = tid>>3 (0..31), kq = tid&7 (float4 of k)
    const int row = tid >> 3;
    const int kq  = tid & 7;
    const float* xsrc = x + (size_t)(row0 + row) * DDIM + kq * 4;
    const int conv_off = ((row >> 4) * 2 + (kq >> 2)) * 512 +
                         (4 * (row & 7) + 2 * (kq & 1)) * 16 +
                         ((row >> 3) & 1) * 4 + ((kq >> 1) & 1) * 8;

    float acc[2][8][4];
    #pragma unroll
    for (int i = 0; i < 2; i++)
        #pragma unroll
        for (int j = 0; j < 8; j++)
            #pragma unroll
            for (int q = 0; q < 4; q++) acc[i][j][q] = 0.f;
    float bacc = 0.f;

    // preload Wb + bh
    #pragma unroll
    for (int i = 0; i < 4; i++) wb_s[tid + 256 * i] = Wb[tid + 256 * i];
    bh_s[tid]       = bh[tid];
    bh_s[tid + 256] = bh[tid + 256];

    // B fragments for chunk 0
    uint4 LB[8];
    #pragma unroll
    for (int j = 0; j < 8; j++)
        LB[j] = *(const uint4*)(bgm + j * 512);

    __syncthreads();   // wb_s visible

    // chunk0 convert + base; prefetch x chunk1
    float4 px = *(const float4*)(xsrc);
    {
        const float4 wv = *(const float4*)(wb_s + kq * 4);
        bacc = fmaf(px.x, wv.x, bacc); bacc = fmaf(px.y, wv.y, bacc);
        bacc = fmaf(px.z, wv.z, bacc); bacc = fmaf(px.w, wv.w, bacc);
        *(__half2*)(smc + XS_O + conv_off)      = __floats2half2_rn(px.x, px.y);
        *(__half2*)(smc + XS_O + conv_off + 16) = __floats2half2_rn(px.z, px.w);
    }
    px = *(const float4*)(xsrc + KCHUNK);

    #pragma unroll 1
    for (int c = 0; c < NCH; c++) {
        __syncthreads();   // xs(c) visible; xs((c+1)&1) free to overwrite

        if (c + 1 < NCH) {   // base fma + convert chunk c+1 from px regs
            const float4 wv = *(const float4*)(wb_s + (c + 1) * KCHUNK + kq * 4);
            bacc = fmaf(px.x, wv.x, bacc); bacc = fmaf(px.y, wv.y, bacc);
            bacc = fmaf(px.z, wv.z, bacc); bacc = fmaf(px.w, wv.w, bacc);
            char* xb = smc + XS_O + ((c + 1) & 1) * 2048 + conv_off;
            *(__half2*)(xb)      = __floats2half2_rn(px.x, px.y);
            *(__half2*)(xb + 16) = __floats2half2_rn(px.z, px.w);
        }
        if (c + 2 < NCH)
            px = *(const float4*)(xsrc + (c + 2) * KCHUNK);

        // ---- MMA chunk c with interleaved consume-then-reload of LB[j] ----
        // (tail chunk harmlessly reloads its own chunk)
        const char* bsrc_next =
            bgm + (size_t)((c + 1 < NCH) ? (c + 1) : c) * 32768;

        const char* xaddr = smc + XS_O + (c & 1) * 2048 + lane * 16;
        uint4 LA00 = *(const uint4*)(xaddr);            // i0 G0
        uint4 LA01 = *(const uint4*)(xaddr + 512);      // i0 G1
        uint4 LA10 = *(const uint4*)(xaddr + 1024);     // i1 G0
        uint4 LA11 = *(const uint4*)(xaddr + 1536);     // i1 G1
        #pragma unroll
        for (int j = 0; j < 8; j++) {
            uint4 b = LB[j];
            mma_f16(acc[0][j], LA00.x, LA00.y, LA00.z, LA00.w, b.x, b.y);
            mma_f16(acc[1][j], LA10.x, LA10.y, LA10.z, LA10.w, b.x, b.y);
            mma_f16(acc[0][j], LA01.x, LA01.y, LA01.z, LA01.w, b.z, b.w);
            mma_f16(acc[1][j], LA11.x, LA11.y, LA11.z, LA11.w, b.z, b.w);
            LB[j] = *(const uint4*)(bsrc_next + j * 512);   // ~1 chunk of slack
        }
    }

    // ---- base reduce: 8 lanes (kq) per row ----
    bacc += __shfl_down_sync(0xffffffffu, bacc, 4, 8);
    bacc += __shfl_down_sync(0xffffffffu, bacc, 2, 8);
    bacc += __shfl_down_sync(0xffffffffu, bacc, 1, 8);
    if (kq == 0) base_s[row] = bacc;

    // ---- per-row segmented scan over this warp's 64 cols ----
    float2 bhv[8];
    #pragma unroll
    for (int j = 0; j < 8; j++)
        bhv[j] = *(const float2*)(bh_s + nw * 64 + 8 * j + 2 * lk);

    #pragma unroll
    for (int i = 0; i < 2; i++) {
        #pragma unroll
        for (int hh = 0; hh < 2; hh++) {
            const int r = 16 * i + 8 * hh + l4;
            float carry = 0.f;
            #pragma unroll
            for (int j = 0; j < 8; j++) {
                float v0 = fmaxf(acc[i][j][2 * hh]     + bhv[j].x, 0.f);
                float v1 = fmaxf(acc[i][j][2 * hh + 1] + bhv[j].y, 0.f);
                float p = v0 + v1;
                float incl = p, t;
                t = __shfl_up_sync(0xffffffffu, incl, 1, 4); if (lk >= 1) incl += t;
                t = __shfl_up_sync(0xffffffffu, incl, 2, 4); if (lk >= 2) incl += t;
                float excl = incl - p;
                acc[i][j][2 * hh]     = carry + excl + v0;
                acc[i][j][2 * hh + 1] = carry + incl;
                carry += __shfl_sync(0xffffffffu, incl, 3, 4);
            }
            if (lk == 0) seg_s[r * 8 + nw] = carry;
        }
    }
    __syncthreads();

    // ---- cross-warp segment prefix + base, store ----
    const float bbv = bb[0];
    #pragma unroll
    for (int i = 0; i < 2; i++) {
        #pragma unroll
        for (int hh = 0; hh < 2; hh++) {
            const int r = 16 * i + 8 * hh + l4;
            float g = base_s[r] + bbv;
            #pragma unroll
            for (int s = 0; s < 8; s++)
                if (s < nw) g += seg_s[r * 8 + s];
            float* orow = out + (size_t)(row0 + r) * TDIM + nw * 64 + 2 * lk;
            #pragma unroll
            for (int j = 0; j < 8; j++) {
                float2 o;
                o.x = acc[i][j][2 * hh]     + g;
                o.y = acc[i][j][2 * hh + 1] + g;
                *(float2*)(orow + 8 * j) = o;
            }
        }
    }
}

extern "C" void kernel_launch(void* const* d_in, const int* in_sizes, int n_in,
                              void* d_out, int out_size)
{
    const float* x  = (const float*)d_in[0];
    const float* Wh = (const float*)d_in[1];
    const float* bh = (const float*)d_in[2];
    const float* Wb = (const float*)d_in[3];
    const float* bb = (const float*)d_in[4];
    float* out = (float*)d_out;
    (void)in_sizes; (void)n_in; (void)out_size;

    prep_wh_kernel<<<TDIM, 256>>>(Wh);
    surv_f16e_kernel<<<BROWS / MTILE, NTHREADS>>>(x, bh, Wb, bb, out);
}